// round 7
// baseline (speedup 1.0000x reference)
#include <cuda_runtime.h>
#include <math.h>

#define DDIM 2048
#define DEPTH 9
#define BM 64
#define BN 64
#define BK 16
#define TM 4
#define TN 4
#define NCHUNK 4
#define CHUNK (DDIM / NCHUNK)   // 512

// Scratch (no allocation allowed) — ping-pong activation buffers + u vectors.
__device__ float g_buf0[(size_t)DDIM * DDIM];
__device__ float g_buf1[(size_t)DDIM * DDIM];
__device__ float g_u1[DDIM];
__device__ float g_u2[DDIM];

// u[j] = (1/n) * (prod_{d,g} cos(uw[d, j, g]))^2   (closed form of _ultimate:
// the initial state is constant along axis 1, so the roll terms cancel exactly
// and each gate scales row i by cos(a_i); value ~1e-10, negligible vs sigma~4.6e4
// pre-activations, but computed faithfully anyway)
__global__ void ultimate_u_kernel(const float* __restrict__ uw, float* __restrict__ u) {
    int j = blockIdx.x * blockDim.x + threadIdx.x;
    if (j >= DDIM) return;
    float p = 1.0f;
#pragma unroll
    for (int d = 0; d < DEPTH; d++) {
        size_t base = (size_t)d * DDIM * DDIM + (size_t)j * DDIM;
        p *= cosf(uw[base + 0]);
        p *= cosf(uw[base + 1]);
        p *= cosf(uw[base + 2]);
    }
    u[j] = p * p * (1.0f / (float)DDIM);
}

// MODE 0: C = relu(A @ W^T + bias)          W is [N,K] row-major, use W[n,k]
// MODE 1: C = tanh(A @ W + bias + u)        W is [K,N] row-major, use W[k,n]
// Accumulation replicates split-K=4: serial fp32 FMA (increasing k) within each
// contiguous 512-chunk, partials combined in chunk order.
template <int MODE>
__global__ __launch_bounds__(256) void gemm_kernel(
    const float* __restrict__ A, const float* __restrict__ W,
    const float* __restrict__ bias, const float* __restrict__ u,
    float* __restrict__ C)
{
    __shared__ float As[BK][BM + 4];
    __shared__ float Bs[BK][BN + 4];

    const int tid = threadIdx.x;
    const int tx = tid & 15;         // 0..15 -> N direction
    const int ty = tid >> 4;         // 0..15 -> M direction
    const int m0 = blockIdx.y * BM;
    const int n0 = blockIdx.x * BN;

    float part[NCHUNK - 1][TM][TN];  // finished chunk partials
    float acc[TM][TN];               // live chunk accumulator

#pragma unroll
    for (int i = 0; i < TM; i++)
#pragma unroll
        for (int j = 0; j < TN; j++) acc[i][j] = 0.0f;

    for (int chunk = 0; chunk < NCHUNK; chunk++) {
        const int kbeg = chunk * CHUNK;
        for (int k0 = kbeg; k0 < kbeg + CHUNK; k0 += BK) {
            // ---- load A tile: rows m0..m0+63, cols k0..k0+15, store transposed
            {
                int r  = tid >> 2;                 // 0..63 (row within tile)
                int c4 = tid & 3;                  // float4 group along k
                float4 v = *(const float4*)(A + (size_t)(m0 + r) * DDIM + k0 + c4 * 4);
                As[c4 * 4 + 0][r] = v.x;
                As[c4 * 4 + 1][r] = v.y;
                As[c4 * 4 + 2][r] = v.z;
                As[c4 * 4 + 3][r] = v.w;
            }
            // ---- load B tile
            if (MODE == 0) {
                // NT: W[n,k], rows n0..n0+63, cols k0..k0+15 -> transpose into Bs[k][n]
                int r  = tid >> 2;
                int c4 = tid & 3;
                float4 v = *(const float4*)(W + (size_t)(n0 + r) * DDIM + k0 + c4 * 4);
                Bs[c4 * 4 + 0][r] = v.x;
                Bs[c4 * 4 + 1][r] = v.y;
                Bs[c4 * 4 + 2][r] = v.z;
                Bs[c4 * 4 + 3][r] = v.w;
            } else {
                // NN: W[k,n], rows k0..k0+15, cols n0..n0+63 -> direct copy
                int r  = tid >> 4;                 // 0..15 (k)
                int c4 = tid & 15;                 // 0..15 (float4 group along n)
                float4 v = *(const float4*)(W + (size_t)(k0 + r) * DDIM + n0 + c4 * 4);
                *(float4*)&Bs[r][c4 * 4] = v;      // (BN+4)=68 floats/row: 16B-aligned
            }
            __syncthreads();

#pragma unroll
            for (int k = 0; k < BK; k++) {
                float a[TM], b[TN];
                *(float4*)&a[0] = *(const float4*)&As[k][ty * TM];
                *(float4*)&b[0] = *(const float4*)&Bs[k][tx * TN];
#pragma unroll
                for (int i = 0; i < TM; i++)
#pragma unroll
                    for (int j = 0; j < TN; j++)
                        acc[i][j] = fmaf(a[i], b[j], acc[i][j]);
            }
            __syncthreads();
        }
        // close out this chunk's partial, reset the live accumulator
        if (chunk < NCHUNK - 1) {
#pragma unroll
            for (int i = 0; i < TM; i++)
#pragma unroll
                for (int j = 0; j < TN; j++) {
                    part[chunk][i][j] = acc[i][j];
                    acc[i][j] = 0.0f;
                }
        }
    }

    // ---- combine partials in chunk order: ((p0 + p1) + p2) + p3
    float sum[TM][TN];
#pragma unroll
    for (int i = 0; i < TM; i++)
#pragma unroll
        for (int j = 0; j < TN; j++) {
            float s = part[0][i][j];
            s = s + part[1][i][j];
            s = s + part[2][i][j];
            s = s + acc[i][j];
            sum[i][j] = s;
        }

    // ---- fused epilogue
#pragma unroll
    for (int i = 0; i < TM; i++) {
        int row = m0 + ty * TM + i;
        int col = n0 + tx * TN;
        float4 v;
        v.x = sum[i][0] + bias[col + 0];
        v.y = sum[i][1] + bias[col + 1];
        v.z = sum[i][2] + bias[col + 2];
        v.w = sum[i][3] + bias[col + 3];
        if (MODE == 1) {
            v.x = tanhf(v.x + u[col + 0]);
            v.y = tanhf(v.y + u[col + 1]);
            v.z = tanhf(v.z + u[col + 2]);
            v.w = tanhf(v.w + u[col + 3]);
        } else {
            v.x = fmaxf(v.x, 0.0f);
            v.y = fmaxf(v.y, 0.0f);
            v.z = fmaxf(v.z, 0.0f);
            v.w = fmaxf(v.w, 0.0f);
        }
        *(float4*)(C + (size_t)row * DDIM + col) = v;
    }
}

extern "C" void kernel_launch(void* const* d_in, const int* in_sizes, int n_in,
                              void* d_out, int out_size) {
    const float* x   = (const float*)d_in[0];
    const float* w0  = (const float*)d_in[1];
    const float* b0  = (const float*)d_in[2];
    const float* w1  = (const float*)d_in[3];
    const float* b1  = (const float*)d_in[4];
    const float* uw1 = (const float*)d_in[5];
    const float* cw1 = (const float*)d_in[6];
    const float* cb1 = (const float*)d_in[7];
    const float* w2  = (const float*)d_in[8];
    const float* b2  = (const float*)d_in[9];
    const float* uw2 = (const float*)d_in[10];
    const float* cw2 = (const float*)d_in[11];
    const float* cb2 = (const float*)d_in[12];
    const float* wf  = (const float*)d_in[13];
    const float* bf  = (const float*)d_in[14];
    float* out = (float*)d_out;

    float *buf0, *buf1, *u1, *u2;
    cudaGetSymbolAddress((void**)&buf0, g_buf0);
    cudaGetSymbolAddress((void**)&buf1, g_buf1);
    cudaGetSymbolAddress((void**)&u1, g_u1);
    cudaGetSymbolAddress((void**)&u2, g_u2);

    dim3 grid(DDIM / BN, DDIM / BM);
    dim3 block(256);

    // closed-form "quantum" vectors
    ultimate_u_kernel<<<DDIM / 256, 256>>>(uw1, u1);
    ultimate_u_kernel<<<DDIM / 256, 256>>>(uw2, u2);

    // 1) h = relu(x @ w0^T + b0)
    gemm_kernel<0><<<grid, block>>>(x, w0, b0, nullptr, buf0);
    // 2) h = relu(h @ w1^T + b1)
    gemm_kernel<0><<<grid, block>>>(buf0, w1, b1, nullptr, buf1);
    // 3) h = tanh(h @ cw1 + cb1 + u1)
    gemm_kernel<1><<<grid, block>>>(buf1, cw1, cb1, u1, buf0);
    // 4) h = relu(h @ w2^T + b2)
    gemm_kernel<0><<<grid, block>>>(buf0, w2, b2, nullptr, buf1);
    // 5) h = tanh(h @ cw2 + cb2 + u2)
    gemm_kernel<1><<<grid, block>>>(buf1, cw2, cb2, u2, buf0);
    // 6) out = relu(h @ wf^T + bf)
    gemm_kernel<0><<<grid, block>>>(buf0, wf, bf, nullptr, out);
}